// round 11
// baseline (speedup 1.0000x reference)
#include <cuda_runtime.h>
#include <cuda_fp16.h>
#include <cstdint>

#define B_SZ  4
#define N_SEQ 2048
#define DIM   512
#define NH    8
#define DK    64
#define M_ROWS (B_SZ * N_SEQ)
#define SCALE 0.125f

// Scratch: projected Q (pre-scaled for tanh-sigmoid), K, V (= x), fp16 weights.
__device__ __half g_Q[M_ROWS * DIM];
__device__ __half g_K[M_ROWS * DIM];
__device__ __half g_V[M_ROWS * DIM];
__device__ __half g_Wq[DIM * DIM];
__device__ __half g_Wk[DIM * DIM];

// ---------------------------------------------------------------------------
// helpers (portable PTX, sm_80-class only)
// ---------------------------------------------------------------------------
__device__ __forceinline__ uint32_t su32(const void* p) {
    uint32_t a;
    asm("{ .reg .u64 t; cvta.to.shared.u64 t, %1; cvt.u32.u64 %0, t; }" : "=r"(a) : "l"(p));
    return a;
}
#define CPA(sa, gp) asm volatile("cp.async.cg.shared.global [%0], [%1], 16;" :: "r"(sa), "l"(gp))
#define CPC()  asm volatile("cp.async.commit_group;" ::: "memory")
#define CPW(n) asm volatile("cp.async.wait_group %0;" :: "n"(n) : "memory")

__device__ __forceinline__ void mma16(float* d, const uint32_t* a, uint32_t b0, uint32_t b1) {
    asm volatile(
        "mma.sync.aligned.m16n8k16.row.col.f32.f16.f16.f32 "
        "{%0,%1,%2,%3}, {%4,%5,%6,%7}, {%8,%9}, {%0,%1,%2,%3};"
        : "+f"(d[0]), "+f"(d[1]), "+f"(d[2]), "+f"(d[3])
        : "r"(a[0]), "r"(a[1]), "r"(a[2]), "r"(a[3]), "r"(b0), "r"(b1));
}
#define LDSM4(r0, r1, r2, r3, addr)                                            \
    asm volatile("ldmatrix.sync.aligned.m8n8.x4.shared.b16 {%0,%1,%2,%3}, [%4];" \
        : "=r"(r0), "=r"(r1), "=r"(r2), "=r"(r3) : "r"(addr))
#define LDSM4T(r0, r1, r2, r3, addr)                                           \
    asm volatile("ldmatrix.sync.aligned.m8n8.x4.trans.shared.b16 {%0,%1,%2,%3}, [%4];" \
        : "=r"(r0), "=r"(r1), "=r"(r2), "=r"(r3) : "r"(addr))

// Inputs already carry the 0.5 factor (folded into Q projection):
// P = 0.5*tanh(S_half) + 0.5 where S_half = 0.5*S_orig.
__device__ __forceinline__ uint32_t sig2(float lo, float hi) {
    __half2 v = __floats2half2_rn(lo, hi);
    uint32_t u = *reinterpret_cast<uint32_t*>(&v);
    uint32_t t;
    asm("tanh.approx.f16x2 %0, %1;" : "=r"(t) : "r"(u));
    __half2 th = *reinterpret_cast<__half2*>(&t);
    __half2 hf = __floats2half2_rn(0.5f, 0.5f);
    __half2 r = __hfma2(th, hf, hf);
    return *reinterpret_cast<uint32_t*>(&r);
}

// ---------------------------------------------------------------------------
// prep: x (f32) -> g_V (fp16) ; Wq,Wk (f32) -> g_Wq,g_Wk (fp16)
// ---------------------------------------------------------------------------
#define NX  (M_ROWS * DIM / 4)
#define NW  (DIM * DIM / 4)
__global__ __launch_bounds__(256) void prep(const float* __restrict__ x,
                                            const float* __restrict__ Wq,
                                            const float* __restrict__ Wk) {
    const int i = blockIdx.x * 256 + threadIdx.x;
    const float* src;
    __half* dst;
    int j;
    if (i < NX)             { src = x;  dst = g_V;  j = i; }
    else if (i < NX + NW)   { src = Wq; dst = g_Wq; j = i - NX; }
    else                    { src = Wk; dst = g_Wk; j = i - NX - NW; }
    float4 v = reinterpret_cast<const float4*>(src)[j];
    __half2 h0 = __floats2half2_rn(v.x, v.y);
    __half2 h1 = __floats2half2_rn(v.z, v.w);
    uint2 u;
    u.x = *reinterpret_cast<uint32_t*>(&h0);
    u.y = *reinterpret_cast<uint32_t*>(&h1);
    reinterpret_cast<uint2*>(dst)[j] = u;
}

// ---------------------------------------------------------------------------
// Projection, fp16 mma + ldmatrix. Q epilogue folds the tanh 0.5 factor:
// g_Q = h((x@Wq)*SCALE*0.5 + 0.5*bias), g_K = h(x@Wk)
// ---------------------------------------------------------------------------
#define P2_AS 72
#define P2_BS 136
#define P2_A_SZ (128 * P2_AS)
#define P2_B_SZ (64 * P2_BS)
#define P2_SMEM ((2 * P2_A_SZ + 2 * P2_B_SZ) * 2)

__global__ __launch_bounds__(256) void proj_tc(const float* __restrict__ bias)
{
    extern __shared__ __half smh[];
    const uint32_t sb = su32(smh);
    const uint32_t sA = sb;
    const uint32_t sB = sb + (uint32_t)(2 * P2_A_SZ) * 2u;

    const int which = blockIdx.z;
    const __half* W = which ? g_Wk : g_Wq;
    __half* outp = which ? g_K : g_Q;

    const int tid = threadIdx.x;
    const int wid = tid >> 5, lane = tid & 31;
    const int g = lane >> 2, t = lane & 3;
    const int rg = wid >> 1, cg = wid & 1;
    const int row0 = blockIdx.y * 128, col0 = blockIdx.x * 128;

    const int lq = lane >> 3, lr = lane & 7;
    const int a_row = ((lq >> 1) << 3) + lr;
    const int a_col = (lq & 1) << 3;
    const int b_row = ((lq & 1) << 3) + lr;
    const int b_col = (lq >> 1) << 3;

    #define P2_LOAD(kt, buf) do {                                               \
        const __half* _sa = g_V + (size_t)row0 * DIM + (kt) * 64;               \
        uint32_t _da = sA + (uint32_t)((buf) * P2_A_SZ) * 2u;                   \
        _Pragma("unroll")                                                       \
        for (int i = 0; i < 4; i++) {                                           \
            int c = tid + i * 256, r = c >> 3, c8 = (c & 7) << 3;               \
            CPA(_da + (uint32_t)(r * P2_AS + c8) * 2u, _sa + (size_t)r * DIM + c8); \
        }                                                                       \
        const __half* _sb = W + (size_t)((kt) * 64) * DIM + col0;               \
        uint32_t _db = sB + (uint32_t)((buf) * P2_B_SZ) * 2u;                   \
        _Pragma("unroll")                                                       \
        for (int i = 0; i < 4; i++) {                                           \
            int c = tid + i * 256, r = c >> 4, c8 = (c & 15) << 3;              \
            CPA(_db + (uint32_t)(r * P2_BS + c8) * 2u, _sb + (size_t)r * DIM + c8); \
        }                                                                       \
        CPC();                                                                  \
    } while (0)

    float C[2][8][4] = {};

    P2_LOAD(0, 0);
    for (int kt = 0; kt < 8; kt++) {
        const int buf = kt & 1;
        if (kt < 7) { P2_LOAD(kt + 1, buf ^ 1); CPW(1); } else { CPW(0); }
        __syncthreads();
        const uint32_t Ab = sA + (uint32_t)(buf * P2_A_SZ) * 2u;
        const uint32_t Bb = sB + (uint32_t)(buf * P2_B_SZ) * 2u;
#pragma unroll
        for (int kb = 0; kb < 4; kb++) {
            const int k0 = kb * 16;
            uint32_t af[2][4];
#pragma unroll
            for (int f = 0; f < 2; f++) {
                uint32_t r0, r1, r2, r3;
                LDSM4(r0, r1, r2, r3,
                      Ab + (uint32_t)((rg * 32 + f * 16 + a_row) * P2_AS + k0 + a_col) * 2u);
                af[f][0] = r0; af[f][1] = r2; af[f][2] = r1; af[f][3] = r3;
            }
#pragma unroll
            for (int nf2 = 0; nf2 < 4; nf2++) {
                uint32_t r0, r1, r2, r3;
                LDSM4T(r0, r1, r2, r3,
                       Bb + (uint32_t)((k0 + b_row) * P2_BS + cg * 64 + nf2 * 16 + b_col) * 2u);
                mma16(C[0][2 * nf2],     af[0], r0, r1);
                mma16(C[0][2 * nf2 + 1], af[0], r2, r3);
                mma16(C[1][2 * nf2],     af[1], r0, r1);
                mma16(C[1][2 * nf2 + 1], af[1], r2, r3);
            }
        }
        __syncthreads();
    }

#pragma unroll
    for (int f = 0; f < 2; f++) {
        const int r = row0 + rg * 32 + f * 16 + g;
#pragma unroll
        for (int cf = 0; cf < 8; cf++) {
            const int cb = col0 + cg * 64 + cf * 8 + 2 * t;
            float v0 = C[f][cf][0], v1 = C[f][cf][1], v2 = C[f][cf][2], v3 = C[f][cf][3];
            if (which == 0) {
                const float hs = 0.5f * SCALE;
                v0 = v0 * hs + 0.5f * bias[cb];     v1 = v1 * hs + 0.5f * bias[cb + 1];
                v2 = v2 * hs + 0.5f * bias[cb];     v3 = v3 * hs + 0.5f * bias[cb + 1];
            }
            *(__half2*)&outp[(size_t)r * DIM + cb]       = __floats2half2_rn(v0, v1);
            *(__half2*)&outp[(size_t)(r + 8) * DIM + cb] = __floats2half2_rn(v2, v3);
        }
    }
}

// ---------------------------------------------------------------------------
// Fused sigmoid attention, SINGLE-WAVE version: occupancy 4 (512 CTAs fit in
// 148 SMs x 4 slots = 592, no tail wave). Regs <= 128 via: Q fragments re-read
// from smem by ldmatrix (not cached in regs), 32-key S blocks. Ring-2 K/V.
// smem: Q[128][72] + 2x(K+V)[64][72] halves = 55,296 B -> 4 CTAs/SM.
// ---------------------------------------------------------------------------
#define KT  64
#define NT  (N_SEQ / KT)
#define KS  72
#define K_BUF (KT * KS)               // 4608 halves
#define VOFF  (2 * K_BUF)
#define QOFF  (4 * K_BUF)             // 18432 halves
#define AT_SMEM ((QOFF + 128 * KS) * 2)   // 55,296 B

__global__ __launch_bounds__(128, 4) void attn_tc(float* __restrict__ out)
{
    extern __shared__ __half smh[];
    const uint32_t sb = su32(smh);
    const int tid = threadIdx.x;
    const int wid = tid >> 5, lane = tid & 31;
    const int g = lane >> 2, t = lane & 3;

    const int it = blockIdx.x, h = blockIdx.y, b = blockIdx.z;
    const size_t base = (size_t)b * N_SEQ * DIM + (size_t)h * DK;
    const __half* qgm = g_Q + base + (size_t)(it * 128) * DIM;
    const __half* kgm = g_K + base;
    const __half* vgm = g_V + base;

    const int lq = lane >> 3, lr = lane & 7;
    const int a_row = ((lq >> 1) << 3) + lr;     // non-trans ldsm (Q and K)
    const int a_col = (lq & 1) << 3;
    const int v_row = ((lq & 1) << 3) + lr;      // trans ldsm (V)
    const int v_col = (lq >> 1) << 3;

    // ---- Q tile [128][64] -> smem (once) ----
    {
        const uint32_t qd = sb + (uint32_t)QOFF * 2u;
#pragma unroll
        for (int i = 0; i < 8; i++) {
            int c = tid + i * 128, r = c >> 3, c8 = (c & 7) << 3;
            CPA(qd + (uint32_t)(r * KS + c8) * 2u, qgm + (size_t)r * DIM + c8);
        }
    }

    #define LOAD_ONE(jt_) do {                                                  \
        const int _buf = (jt_) & 1;                                             \
        const __half* _ks = kgm + (size_t)((jt_) * KT) * DIM;                   \
        const __half* _vs = vgm + (size_t)((jt_) * KT) * DIM;                   \
        uint32_t _kd = sb + (uint32_t)(_buf * K_BUF) * 2u;                      \
        uint32_t _vd = sb + (uint32_t)(VOFF + _buf * K_BUF) * 2u;               \
        _Pragma("unroll")                                                       \
        for (int i = 0; i < 4; i++) {                                           \
            int c = tid + i * 128, r = c >> 3, c8 = (c & 7) << 3;               \
            CPA(_kd + (uint32_t)(r * KS + c8) * 2u, _ks + (size_t)r * DIM + c8);\
            CPA(_vd + (uint32_t)(r * KS + c8) * 2u, _vs + (size_t)r * DIM + c8);\
        }                                                                       \
        CPC();                                                                  \
    } while (0)

    LOAD_ONE(0);   // groups: {Q + tile0}

    // per-strip Q ldmatrix base address (strip s covers rows wid*32+s*16..+15)
    uint32_t qb[2];
#pragma unroll
    for (int s = 0; s < 2; s++)
        qb[s] = sb + (uint32_t)(QOFF + (wid * 32 + s * 16 + a_row) * KS + a_col) * 2u;

    float O[2][8][4] = {};

    for (int jt = 0; jt < NT; jt++) {
        CPW(0);
        __syncthreads();   // tile jt (and Q on jt=0) visible; buf (jt+1)&1 free
        if (jt + 1 < NT) LOAD_ONE(jt + 1);

        const uint32_t ksb = sb + (uint32_t)((jt & 1) * K_BUF) * 2u;
        const uint32_t vsb = sb + (uint32_t)((VOFF + (jt & 1) * K_BUF)) * 2u;

        // process 32-key halves: GEMM1 block -> sigmoid -> GEMM2 block
#pragma unroll
        for (int half = 0; half < 2; half++) {
            const int n0 = half * 32;

            // ---- GEMM1: Sb(32 rows x 32 keys) = Q K^T ----
            float Sb[2][2][2][4] = {};   // [strip][g16][colfrag][4]
#pragma unroll
            for (int kb = 0; kb < 4; kb++) {
                uint32_t qa[2][4];
#pragma unroll
                for (int s = 0; s < 2; s++) {
                    uint32_t r0, r1, r2, r3;
                    LDSM4(r0, r1, r2, r3, qb[s] + (uint32_t)(kb * 16 * 2));
                    qa[s][0] = r0; qa[s][1] = r2; qa[s][2] = r1; qa[s][3] = r3;
                }
#pragma unroll
                for (int g16 = 0; g16 < 2; g16++) {
                    const int nn = n0 + g16 * 16;
                    uint32_t r0, r1, r2, r3;
                    LDSM4(r0, r1, r2, r3,
                          ksb + (uint32_t)((nn + a_row) * KS + kb * 16 + a_col) * 2u);
#pragma unroll
                    for (int s = 0; s < 2; s++) {
                        mma16(Sb[s][g16][0], qa[s], r0, r1);
                        mma16(Sb[s][g16][1], qa[s], r2, r3);
                    }
                }
            }

            // ---- sigmoid -> A-fragments (0.5 pre-folded into Q) ----
            uint32_t pb[2][2][4];
#pragma unroll
            for (int s = 0; s < 2; s++)
#pragma unroll
                for (int g16 = 0; g16 < 2; g16++) {
                    pb[s][g16][0] = sig2(Sb[s][g16][0][0], Sb[s][g16][0][1]);
                    pb[s][g16][1] = sig2(Sb[s][g16][0][2], Sb[s][g16][0][3]);
                    pb[s][g16][2] = sig2(Sb[s][g16][1][0], Sb[s][g16][1][1]);
                    pb[s][g16][3] = sig2(Sb[s][g16][1][2], Sb[s][g16][1][3]);
                }

            // ---- GEMM2: O(32x64) += P(:, n0:n0+32) V(n0:n0+32, :) ----
#pragma unroll
            for (int g16 = 0; g16 < 2; g16++) {
                const int nn = n0 + g16 * 16;
#pragma unroll
                for (int nv = 0; nv < 4; nv++) {
                    uint32_t r0, r1, r2, r3;
                    LDSM4T(r0, r1, r2, r3,
                           vsb + (uint32_t)((nn + v_row) * KS + nv * 16 + v_col) * 2u);
#pragma unroll
                    for (int s = 0; s < 2; s++) {
                        mma16(O[s][2 * nv],     pb[s][g16], r0, r1);
                        mma16(O[s][2 * nv + 1], pb[s][g16], r2, r3);
                    }
                }
            }
        }
    }

    // ---- epilogue ----
#pragma unroll
    for (int s = 0; s < 2; s++) {
        const int r0 = it * 128 + wid * 32 + s * 16 + g;
        float* og = out + ((size_t)b * N_SEQ + r0) * DIM + h * DK;
#pragma unroll
        for (int nf = 0; nf < 8; nf++) {
            const int d = nf * 8 + 2 * t;
            *(float2*)&og[d] = make_float2(O[s][nf][0], O[s][nf][1]);
            *(float2*)(og + (size_t)8 * DIM + d) = make_float2(O[s][nf][2], O[s][nf][3]);
        }
    }
}

extern "C" void kernel_launch(void* const* d_in, const int* in_sizes, int n_in,
                              void* d_out, int out_size)
{
    const float* x    = (const float*)d_in[0];
    const float* Wq   = (const float*)d_in[1];
    const float* Wk   = (const float*)d_in[2];
    const float* bias = (const float*)d_in[3];
    float* out = (float*)d_out;

    cudaFuncSetAttribute(proj_tc, cudaFuncAttributeMaxDynamicSharedMemorySize, P2_SMEM);
    cudaFuncSetAttribute(attn_tc, cudaFuncAttributeMaxDynamicSharedMemorySize, AT_SMEM);

    prep<<<(NX + 2 * NW + 255) / 256, 256>>>(x, Wq, Wk);
    proj_tc<<<dim3(DIM / 128, M_ROWS / 128, 2), 256, P2_SMEM>>>(bias);
    attn_tc<<<dim3(N_SEQ / 128, NH, B_SZ), 128, AT_SMEM>>>(out);
}

// round 12
// speedup vs baseline: 1.2116x; 1.2116x over previous
#include <cuda_runtime.h>
#include <cuda_fp16.h>
#include <cstdint>

#define B_SZ  4
#define N_SEQ 2048
#define DIM   512
#define NH    8
#define DK    64
#define M_ROWS (B_SZ * N_SEQ)
#define SCALE 0.125f

__device__ __half g_Q[M_ROWS * DIM];
__device__ __half g_K[M_ROWS * DIM];
__device__ __half g_V[M_ROWS * DIM];
__device__ __half g_Wq[DIM * DIM];
__device__ __half g_Wk[DIM * DIM];

// ---------------------------------------------------------------------------
// helpers
// ---------------------------------------------------------------------------
__device__ __forceinline__ uint32_t su32(const void* p) {
    uint32_t a;
    asm("{ .reg .u64 t; cvta.to.shared.u64 t, %1; cvt.u32.u64 %0, t; }" : "=r"(a) : "l"(p));
    return a;
}
#define CPA(sa, gp) asm volatile("cp.async.cg.shared.global [%0], [%1], 16;" :: "r"(sa), "l"(gp))
#define CPC()  asm volatile("cp.async.commit_group;" ::: "memory")
#define CPW(n) asm volatile("cp.async.wait_group %0;" :: "n"(n) : "memory")

__device__ __forceinline__ void mma16(float* d, const uint32_t* a, uint32_t b0, uint32_t b1) {
    asm volatile(
        "mma.sync.aligned.m16n8k16.row.col.f32.f16.f16.f32 "
        "{%0,%1,%2,%3}, {%4,%5,%6,%7}, {%8,%9}, {%0,%1,%2,%3};"
        : "+f"(d[0]), "+f"(d[1]), "+f"(d[2]), "+f"(d[3])
        : "r"(a[0]), "r"(a[1]), "r"(a[2]), "r"(a[3]), "r"(b0), "r"(b1));
}
#define LDSM4(r0, r1, r2, r3, addr)                                            \
    asm volatile("ldmatrix.sync.aligned.m8n8.x4.shared.b16 {%0,%1,%2,%3}, [%4];" \
        : "=r"(r0), "=r"(r1), "=r"(r2), "=r"(r3) : "r"(addr))
#define LDSM4T(r0, r1, r2, r3, addr)                                           \
    asm volatile("ldmatrix.sync.aligned.m8n8.x4.trans.shared.b16 {%0,%1,%2,%3}, [%4];" \
        : "=r"(r0), "=r"(r1), "=r"(r2), "=r"(r3) : "r"(addr))

// Inputs already carry the 0.5 factor (folded into Q projection).
__device__ __forceinline__ uint32_t sig2(float lo, float hi) {
    __half2 v = __floats2half2_rn(lo, hi);
    uint32_t u = *reinterpret_cast<uint32_t*>(&v);
    uint32_t t;
    asm("tanh.approx.f16x2 %0, %1;" : "=r"(t) : "r"(u));
    __half2 th = *reinterpret_cast<__half2*>(&t);
    __half2 hf = __floats2half2_rn(0.5f, 0.5f);
    __half2 r = __hfma2(th, hf, hf);
    return *reinterpret_cast<uint32_t*>(&r);
}

// ---------------------------------------------------------------------------
// prep: x -> g_V, Wq/Wk -> g_Wq/g_Wk (f32->fp16), 4 chunks per thread (MLP=4)
// ---------------------------------------------------------------------------
#define NX  (M_ROWS * DIM / 4)
#define NW  (DIM * DIM / 4)
#define NTOT (NX + 2 * NW)
__global__ __launch_bounds__(256) void prep(const float* __restrict__ x,
                                            const float* __restrict__ Wq,
                                            const float* __restrict__ Wk) {
    const int base = blockIdx.x * 1024 + threadIdx.x;
#pragma unroll
    for (int j = 0; j < 4; j++) {
        const int i = base + j * 256;
        if (i >= NTOT) break;
        const float* src;
        __half* dst;
        int idx;
        if (i < NX)           { src = x;  dst = g_V;  idx = i; }
        else if (i < NX + NW) { src = Wq; dst = g_Wq; idx = i - NX; }
        else                  { src = Wk; dst = g_Wk; idx = i - NX - NW; }
        float4 v = reinterpret_cast<const float4*>(src)[idx];
        __half2 h0 = __floats2half2_rn(v.x, v.y);
        __half2 h1 = __floats2half2_rn(v.z, v.w);
        uint2 u;
        u.x = *reinterpret_cast<uint32_t*>(&h0);
        u.y = *reinterpret_cast<uint32_t*>(&h1);
        reinterpret_cast<uint2*>(dst)[idx] = u;
    }
}

// ---------------------------------------------------------------------------
// Projection, fp16 mma + ldmatrix, RING-3 k-stages, ONE sync per iter.
// g_Q = h((x@Wq)*SCALE*0.5 + 0.5*bias), g_K = h(x@Wk)
// smem: 3 x (A[128][72] + B[64][136]) halves = 107,520 B
// ---------------------------------------------------------------------------
#define P2_AS 72
#define P2_BS 136
#define P2_A_SZ (128 * P2_AS)
#define P2_B_SZ (64 * P2_BS)
#define P2_STG (P2_A_SZ + P2_B_SZ)
#define P2_SMEM (3 * P2_STG * 2)

__global__ __launch_bounds__(256) void proj_tc(const float* __restrict__ bias)
{
    extern __shared__ __half smh[];
    const uint32_t sb = su32(smh);

    const int which = blockIdx.z;
    const __half* W = which ? g_Wk : g_Wq;
    __half* outp = which ? g_K : g_Q;

    const int tid = threadIdx.x;
    const int wid = tid >> 5, lane = tid & 31;
    const int g = lane >> 2, t = lane & 3;
    const int rg = wid >> 1, cg = wid & 1;
    const int row0 = blockIdx.y * 128, col0 = blockIdx.x * 128;

    const int lq = lane >> 3, lr = lane & 7;
    const int a_row = ((lq >> 1) << 3) + lr;
    const int a_col = (lq & 1) << 3;
    const int b_row = ((lq & 1) << 3) + lr;
    const int b_col = (lq >> 1) << 3;

    // stage s: A at sb + s*P2_STG, B at sb + s*P2_STG + P2_A_SZ   (half units)
    #define P2_LOAD(kt, stg) do {                                               \
        const __half* _sa = g_V + (size_t)row0 * DIM + (kt) * 64;               \
        uint32_t _da = sb + (uint32_t)((stg) * P2_STG) * 2u;                    \
        _Pragma("unroll")                                                       \
        for (int i = 0; i < 4; i++) {                                           \
            int c = tid + i * 256, r = c >> 3, c8 = (c & 7) << 3;               \
            CPA(_da + (uint32_t)(r * P2_AS + c8) * 2u, _sa + (size_t)r * DIM + c8); \
        }                                                                       \
        const __half* _sb = W + (size_t)((kt) * 64) * DIM + col0;               \
        uint32_t _db = sb + (uint32_t)((stg) * P2_STG + P2_A_SZ) * 2u;          \
        _Pragma("unroll")                                                       \
        for (int i = 0; i < 4; i++) {                                           \
            int c = tid + i * 256, r = c >> 4, c8 = (c & 15) << 3;              \
            CPA(_db + (uint32_t)(r * P2_BS + c8) * 2u, _sb + (size_t)r * DIM + c8); \
        }                                                                       \
        CPC();                                                                  \
    } while (0)

    float C[2][8][4] = {};

    P2_LOAD(0, 0);
    P2_LOAD(1, 1);

    for (int kt = 0; kt < 8; kt++) {
        const int stg = kt % 3;
        if (kt < 6) { CPW(1); } else { CPW(0); }   // tile kt landed
        __syncthreads();                            // all warps done with stage (kt+2)%3 (= iter kt-1)
        if (kt + 2 < 8) P2_LOAD(kt + 2, (kt + 2) % 3);

        const uint32_t Ab = sb + (uint32_t)(stg * P2_STG) * 2u;
        const uint32_t Bb = sb + (uint32_t)(stg * P2_STG + P2_A_SZ) * 2u;
#pragma unroll
        for (int kb = 0; kb < 4; kb++) {
            const int k0 = kb * 16;
            uint32_t af[2][4];
#pragma unroll
            for (int f = 0; f < 2; f++) {
                uint32_t r0, r1, r2, r3;
                LDSM4(r0, r1, r2, r3,
                      Ab + (uint32_t)((rg * 32 + f * 16 + a_row) * P2_AS + k0 + a_col) * 2u);
                af[f][0] = r0; af[f][1] = r2; af[f][2] = r1; af[f][3] = r3;
            }
#pragma unroll
            for (int nf2 = 0; nf2 < 4; nf2++) {
                uint32_t r0, r1, r2, r3;
                LDSM4T(r0, r1, r2, r3,
                       Bb + (uint32_t)((k0 + b_row) * P2_BS + cg * 64 + nf2 * 16 + b_col) * 2u);
                mma16(C[0][2 * nf2],     af[0], r0, r1);
                mma16(C[0][2 * nf2 + 1], af[0], r2, r3);
                mma16(C[1][2 * nf2],     af[1], r0, r1);
                mma16(C[1][2 * nf2 + 1], af[1], r2, r3);
            }
        }
    }

#pragma unroll
    for (int f = 0; f < 2; f++) {
        const int r = row0 + rg * 32 + f * 16 + g;
#pragma unroll
        for (int cf = 0; cf < 8; cf++) {
            const int cb = col0 + cg * 64 + cf * 8 + 2 * t;
            float v0 = C[f][cf][0], v1 = C[f][cf][1], v2 = C[f][cf][2], v3 = C[f][cf][3];
            if (which == 0) {
                const float hs = 0.5f * SCALE;
                v0 = v0 * hs + 0.5f * bias[cb];     v1 = v1 * hs + 0.5f * bias[cb + 1];
                v2 = v2 * hs + 0.5f * bias[cb];     v3 = v3 * hs + 0.5f * bias[cb + 1];
            }
            *(__half2*)&outp[(size_t)r * DIM + cb]       = __floats2half2_rn(v0, v1);
            *(__half2*)&outp[(size_t)(r + 8) * DIM + cb] = __floats2half2_rn(v2, v3);
        }
    }
}

// ---------------------------------------------------------------------------
// Fused sigmoid attention — EXACT R10 configuration (best: 143.5us).
// 4 warps x 32 Q-rows, per-16-key-block pipeline, ring-4 smem, occ 3.
// ---------------------------------------------------------------------------
#define KT  64
#define NT  (N_SEQ / KT)
#define KS  72
#define K_BUF (KT * KS)
#define VOFF0 (4 * K_BUF)
#define AT_SMEM (8 * K_BUF * 2)

__global__ __launch_bounds__(128, 3) void attn_tc(float* __restrict__ out)
{
    extern __shared__ __half smh[];
    const uint32_t sb = su32(smh);
    const int tid = threadIdx.x;
    const int wid = tid >> 5, lane = tid & 31;
    const int g = lane >> 2, t = lane & 3;

    const int it = blockIdx.x, h = blockIdx.y, b = blockIdx.z;
    const size_t base = (size_t)b * N_SEQ * DIM + (size_t)h * DK;
    const __half* qgm = g_Q + base + (size_t)(it * 128) * DIM;
    const __half* kgm = g_K + base;
    const __half* vgm = g_V + base;

    const int lq = lane >> 3, lr = lane & 7;
    const int k_row = ((lq >> 1) << 3) + lr;
    const int k_col = (lq & 1) << 3;
    const int v_row = ((lq & 1) << 3) + lr;
    const int v_col = (lq >> 1) << 3;

    uint32_t qf[2][4][4];
#pragma unroll
    for (int s = 0; s < 2; s++) {
        const __half* q0 = qgm + (size_t)(wid * 32 + s * 16 + g) * DIM;
        const __half* q1 = q0 + (size_t)8 * DIM;
#pragma unroll
        for (int kb = 0; kb < 4; kb++) {
            qf[s][kb][0] = *(const uint32_t*)(q0 + 16 * kb + 2 * t);
            qf[s][kb][1] = *(const uint32_t*)(q1 + 16 * kb + 2 * t);
            qf[s][kb][2] = *(const uint32_t*)(q0 + 16 * kb + 8 + 2 * t);
            qf[s][kb][3] = *(const uint32_t*)(q1 + 16 * kb + 8 + 2 * t);
        }
    }

    #define LOAD_ONE(jt_) do {                                                  \
        const int _buf = (jt_) & 3;                                             \
        const __half* _ks = kgm + (size_t)((jt_) * KT) * DIM;                   \
        const __half* _vs = vgm + (size_t)((jt_) * KT) * DIM;                   \
        uint32_t _kd = sb + (uint32_t)(_buf * K_BUF) * 2u;                      \
        uint32_t _vd = sb + (uint32_t)(VOFF0 + _buf * K_BUF) * 2u;              \
        _Pragma("unroll")                                                       \
        for (int i = 0; i < 4; i++) {                                           \
            int c = tid + i * 128, r = c >> 3, c8 = (c & 7) << 3;               \
            CPA(_kd + (uint32_t)(r * KS + c8) * 2u, _ks + (size_t)r * DIM + c8);\
            CPA(_vd + (uint32_t)(r * KS + c8) * 2u, _vs + (size_t)r * DIM + c8);\
        }                                                                       \
    } while (0)
    #define LOAD2(jt_) do { LOAD_ONE(jt_); LOAD_ONE((jt_) + 1); CPC(); } while (0)

    float O[2][8][4] = {};

    LOAD2(0);

    for (int jt2 = 0; jt2 < NT; jt2 += 2) {
        CPW(0);
        __syncthreads();
        if (jt2 + 2 < NT) LOAD2(jt2 + 2);

#pragma unroll
        for (int j = 0; j < 2; j++) {
            const int jt = jt2 + j;
            const int buf = jt & 3;
            const uint32_t ksb = sb + (uint32_t)(buf * K_BUF) * 2u;
            const uint32_t vsb = sb + (uint32_t)((VOFF0 + buf * K_BUF)) * 2u;

#pragma unroll
            for (int nf2 = 0; nf2 < 4; nf2++) {
                const int n0 = nf2 * 16;

                float Sb[2][2][4] = {};
#pragma unroll
                for (int kb = 0; kb < 4; kb++) {
                    const int k0 = kb * 16;
                    uint32_t r0, r1, r2, r3;
                    LDSM4(r0, r1, r2, r3,
                          ksb + (uint32_t)((n0 + k_row) * KS + k0 + k_col) * 2u);
#pragma unroll
                    for (int s = 0; s < 2; s++) {
                        mma16(Sb[s][0], qf[s][kb], r0, r1);
                        mma16(Sb[s][1], qf[s][kb], r2, r3);
                    }
                }

                uint32_t pb[2][4];
#pragma unroll
                for (int s = 0; s < 2; s++) {
                    pb[s][0] = sig2(Sb[s][0][0], Sb[s][0][1]);
                    pb[s][1] = sig2(Sb[s][0][2], Sb[s][0][3]);
                    pb[s][2] = sig2(Sb[s][1][0], Sb[s][1][1]);
                    pb[s][3] = sig2(Sb[s][1][2], Sb[s][1][3]);
                }

#pragma unroll
                for (int nv = 0; nv < 4; nv++) {
                    const int n0v = nv * 16;
                    uint32_t r0, r1, r2, r3;
                    LDSM4T(r0, r1, r2, r3,
                           vsb + (uint32_t)((n0 + v_row) * KS + n0v + v_col) * 2u);
#pragma unroll
                    for (int s = 0; s < 2; s++) {
                        mma16(O[s][2 * nv],     pb[s], r0, r1);
                        mma16(O[s][2 * nv + 1], pb[s], r2, r3);
                    }
                }
            }
        }
    }

#pragma unroll
    for (int s = 0; s < 2; s++) {
        const int r0 = it * 128 + wid * 32 + s * 16 + g;
        float* og = out + ((size_t)b * N_SEQ + r0) * DIM + h * DK;
#pragma unroll
        for (int nf = 0; nf < 8; nf++) {
            const int d = nf * 8 + 2 * t;
            *(float2*)&og[d] = make_float2(O[s][nf][0], O[s][nf][1]);
            *(float2*)(og + (size_t)8 * DIM + d) = make_float2(O[s][nf][2], O[s][nf][3]);
        }
    }
}

extern "C" void kernel_launch(void* const* d_in, const int* in_sizes, int n_in,
                              void* d_out, int out_size)
{
    const float* x    = (const float*)d_in[0];
    const float* Wq   = (const float*)d_in[1];
    const float* Wk   = (const float*)d_in[2];
    const float* bias = (const float*)d_in[3];
    float* out = (float*)d_out;

    cudaFuncSetAttribute(proj_tc, cudaFuncAttributeMaxDynamicSharedMemorySize, P2_SMEM);
    cudaFuncSetAttribute(attn_tc, cudaFuncAttributeMaxDynamicSharedMemorySize, AT_SMEM);

    prep<<<(NTOT + 1023) / 1024, 256>>>(x, Wq, Wk);
    proj_tc<<<dim3(DIM / 128, M_ROWS / 128, 2), 256, P2_SMEM>>>(bias);
    attn_tc<<<dim3(N_SEQ / 128, NH, B_SZ), 128, AT_SMEM>>>(out);
}

// round 13
// speedup vs baseline: 1.2170x; 1.0045x over previous
#include <cuda_runtime.h>
#include <cuda_fp16.h>
#include <cstdint>

#define B_SZ  4
#define N_SEQ 2048
#define DIM   512
#define NH    8
#define DK    64
#define M_ROWS (B_SZ * N_SEQ)
#define SCALE 0.125f

__device__ __half g_Q[M_ROWS * DIM];
__device__ __half g_K[M_ROWS * DIM];
__device__ __half g_V[M_ROWS * DIM];
__device__ __half g_Wq[DIM * DIM];
__device__ __half g_Wk[DIM * DIM];

// ---------------------------------------------------------------------------
// helpers
// ---------------------------------------------------------------------------
__device__ __forceinline__ uint32_t su32(const void* p) {
    uint32_t a;
    asm("{ .reg .u64 t; cvta.to.shared.u64 t, %1; cvt.u32.u64 %0, t; }" : "=r"(a) : "l"(p));
    return a;
}
#define CPA(sa, gp) asm volatile("cp.async.cg.shared.global [%0], [%1], 16;" :: "r"(sa), "l"(gp))
#define CPC()  asm volatile("cp.async.commit_group;" ::: "memory")
#define CPW(n) asm volatile("cp.async.wait_group %0;" :: "n"(n) : "memory")

__device__ __forceinline__ void mma16(float* d, const uint32_t* a, uint32_t b0, uint32_t b1) {
    asm volatile(
        "mma.sync.aligned.m16n8k16.row.col.f32.f16.f16.f32 "
        "{%0,%1,%2,%3}, {%4,%5,%6,%7}, {%8,%9}, {%0,%1,%2,%3};"
        : "+f"(d[0]), "+f"(d[1]), "+f"(d[2]), "+f"(d[3])
        : "r"(a[0]), "r"(a[1]), "r"(a[2]), "r"(a[3]), "r"(b0), "r"(b1));
}
#define LDSM4(r0, r1, r2, r3, addr)                                            \
    asm volatile("ldmatrix.sync.aligned.m8n8.x4.shared.b16 {%0,%1,%2,%3}, [%4];" \
        : "=r"(r0), "=r"(r1), "=r"(r2), "=r"(r3) : "r"(addr))
#define LDSM4T(r0, r1, r2, r3, addr)                                           \
    asm volatile("ldmatrix.sync.aligned.m8n8.x4.trans.shared.b16 {%0,%1,%2,%3}, [%4];" \
        : "=r"(r0), "=r"(r1), "=r"(r2), "=r"(r3) : "r"(addr))

// Inputs already carry the 0.5 factor (folded into Q projection).
__device__ __forceinline__ uint32_t sig2(float lo, float hi) {
    __half2 v = __floats2half2_rn(lo, hi);
    uint32_t u = *reinterpret_cast<uint32_t*>(&v);
    uint32_t t;
    asm("tanh.approx.f16x2 %0, %1;" : "=r"(t) : "r"(u));
    __half2 th = *reinterpret_cast<__half2*>(&t);
    __half2 hf = __floats2half2_rn(0.5f, 0.5f);
    __half2 r = __hfma2(th, hf, hf);
    return *reinterpret_cast<uint32_t*>(&r);
}

// ---------------------------------------------------------------------------
// prep: x -> g_V, Wq/Wk -> g_Wq/g_Wk (f32->fp16), ILP 4
// ---------------------------------------------------------------------------
#define NX  (M_ROWS * DIM / 4)
#define NW  (DIM * DIM / 4)
#define NTOT (NX + 2 * NW)
__global__ __launch_bounds__(256) void prep(const float* __restrict__ x,
                                            const float* __restrict__ Wq,
                                            const float* __restrict__ Wk) {
    const int base = blockIdx.x * 1024 + threadIdx.x;
#pragma unroll
    for (int j = 0; j < 4; j++) {
        const int i = base + j * 256;
        if (i >= NTOT) break;
        const float* src;
        __half* dst;
        int idx;
        if (i < NX)           { src = x;  dst = g_V;  idx = i; }
        else if (i < NX + NW) { src = Wq; dst = g_Wq; idx = i - NX; }
        else                  { src = Wk; dst = g_Wk; idx = i - NX - NW; }
        float4 v = reinterpret_cast<const float4*>(src)[idx];
        __half2 h0 = __floats2half2_rn(v.x, v.y);
        __half2 h1 = __floats2half2_rn(v.z, v.w);
        uint2 u;
        u.x = *reinterpret_cast<uint32_t*>(&h0);
        u.y = *reinterpret_cast<uint32_t*>(&h1);
        reinterpret_cast<uint2*>(dst)[idx] = u;
    }
}

// ---------------------------------------------------------------------------
// Projection (R6 2-stage pipeline; grid reordered for A-tile L2 sharing:
// blockIdx.x = col*2 + which, blockIdx.y = row -> the 8 CTAs reading one
// A (x) row-tile are schedule-adjacent).
// g_Q = h((x@Wq)*SCALE*0.5 + 0.5*bias), g_K = h(x@Wk)
// ---------------------------------------------------------------------------
#define P2_AS 72
#define P2_BS 136
#define P2_A_SZ (128 * P2_AS)
#define P2_B_SZ (64 * P2_BS)
#define P2_SMEM ((2 * P2_A_SZ + 2 * P2_B_SZ) * 2)

__global__ __launch_bounds__(256) void proj_tc(const float* __restrict__ bias)
{
    extern __shared__ __half smh[];
    const uint32_t sb = su32(smh);
    const uint32_t sA = sb;
    const uint32_t sB = sb + (uint32_t)(2 * P2_A_SZ) * 2u;

    const int which = blockIdx.x & 1;
    const int colb  = blockIdx.x >> 1;
    const __half* W = which ? g_Wk : g_Wq;
    __half* outp = which ? g_K : g_Q;

    const int tid = threadIdx.x;
    const int wid = tid >> 5, lane = tid & 31;
    const int g = lane >> 2, t = lane & 3;
    const int rg = wid >> 1, cg = wid & 1;
    const int row0 = blockIdx.y * 128, col0 = colb * 128;

    const int lq = lane >> 3, lr = lane & 7;
    const int a_row = ((lq >> 1) << 3) + lr;
    const int a_col = (lq & 1) << 3;
    const int b_row = ((lq & 1) << 3) + lr;
    const int b_col = (lq >> 1) << 3;

    #define P2_LOAD(kt, buf) do {                                               \
        const __half* _sa = g_V + (size_t)row0 * DIM + (kt) * 64;               \
        uint32_t _da = sA + (uint32_t)((buf) * P2_A_SZ) * 2u;                   \
        _Pragma("unroll")                                                       \
        for (int i = 0; i < 4; i++) {                                           \
            int c = tid + i * 256, r = c >> 3, c8 = (c & 7) << 3;               \
            CPA(_da + (uint32_t)(r * P2_AS + c8) * 2u, _sa + (size_t)r * DIM + c8); \
        }                                                                       \
        const __half* _sb = W + (size_t)((kt) * 64) * DIM + col0;               \
        uint32_t _db = sB + (uint32_t)((buf) * P2_B_SZ) * 2u;                   \
        _Pragma("unroll")                                                       \
        for (int i = 0; i < 4; i++) {                                           \
            int c = tid + i * 256, r = c >> 4, c8 = (c & 15) << 3;              \
            CPA(_db + (uint32_t)(r * P2_BS + c8) * 2u, _sb + (size_t)r * DIM + c8); \
        }                                                                       \
        CPC();                                                                  \
    } while (0)

    float C[2][8][4] = {};

    P2_LOAD(0, 0);
    for (int kt = 0; kt < 8; kt++) {
        const int buf = kt & 1;
        if (kt < 7) { P2_LOAD(kt + 1, buf ^ 1); CPW(1); } else { CPW(0); }
        __syncthreads();
        const uint32_t Ab = sA + (uint32_t)(buf * P2_A_SZ) * 2u;
        const uint32_t Bb = sB + (uint32_t)(buf * P2_B_SZ) * 2u;
#pragma unroll
        for (int kb = 0; kb < 4; kb++) {
            const int k0 = kb * 16;
            uint32_t af[2][4];
#pragma unroll
            for (int f = 0; f < 2; f++) {
                uint32_t r0, r1, r2, r3;
                LDSM4(r0, r1, r2, r3,
                      Ab + (uint32_t)((rg * 32 + f * 16 + a_row) * P2_AS + k0 + a_col) * 2u);
                af[f][0] = r0; af[f][1] = r2; af[f][2] = r1; af[f][3] = r3;
            }
#pragma unroll
            for (int nf2 = 0; nf2 < 4; nf2++) {
                uint32_t r0, r1, r2, r3;
                LDSM4T(r0, r1, r2, r3,
                       Bb + (uint32_t)((k0 + b_row) * P2_BS + cg * 64 + nf2 * 16 + b_col) * 2u);
                mma16(C[0][2 * nf2],     af[0], r0, r1);
                mma16(C[0][2 * nf2 + 1], af[0], r2, r3);
                mma16(C[1][2 * nf2],     af[1], r0, r1);
                mma16(C[1][2 * nf2 + 1], af[1], r2, r3);
            }
        }
        __syncthreads();
    }

#pragma unroll
    for (int f = 0; f < 2; f++) {
        const int r = row0 + rg * 32 + f * 16 + g;
#pragma unroll
        for (int cf = 0; cf < 8; cf++) {
            const int cb = col0 + cg * 64 + cf * 8 + 2 * t;
            float v0 = C[f][cf][0], v1 = C[f][cf][1], v2 = C[f][cf][2], v3 = C[f][cf][3];
            if (which == 0) {
                const float hs = 0.5f * SCALE;
                v0 = v0 * hs + 0.5f * bias[cb];     v1 = v1 * hs + 0.5f * bias[cb + 1];
                v2 = v2 * hs + 0.5f * bias[cb];     v3 = v3 * hs + 0.5f * bias[cb + 1];
            }
            *(__half2*)&outp[(size_t)r * DIM + cb]       = __floats2half2_rn(v0, v1);
            *(__half2*)&outp[(size_t)(r + 8) * DIM + cb] = __floats2half2_rn(v2, v3);
        }
    }
}

// ---------------------------------------------------------------------------
// Fused sigmoid attention — EXACT R10 configuration (best measured).
// 4 warps x 32 Q-rows, per-16-key-block pipeline, ring-4 smem, occ 3.
// ---------------------------------------------------------------------------
#define KT  64
#define NT  (N_SEQ / KT)
#define KS  72
#define K_BUF (KT * KS)
#define VOFF0 (4 * K_BUF)
#define AT_SMEM (8 * K_BUF * 2)

__global__ __launch_bounds__(128, 3) void attn_tc(float* __restrict__ out)
{
    extern __shared__ __half smh[];
    const uint32_t sb = su32(smh);
    const int tid = threadIdx.x;
    const int wid = tid >> 5, lane = tid & 31;
    const int g = lane >> 2, t = lane & 3;

    const int it = blockIdx.x, h = blockIdx.y, b = blockIdx.z;
    const size_t base = (size_t)b * N_SEQ * DIM + (size_t)h * DK;
    const __half* qgm = g_Q + base + (size_t)(it * 128) * DIM;
    const __half* kgm = g_K + base;
    const __half* vgm = g_V + base;

    const int lq = lane >> 3, lr = lane & 7;
    const int k_row = ((lq >> 1) << 3) + lr;
    const int k_col = (lq & 1) << 3;
    const int v_row = ((lq & 1) << 3) + lr;
    const int v_col = (lq >> 1) << 3;

    uint32_t qf[2][4][4];
#pragma unroll
    for (int s = 0; s < 2; s++) {
        const __half* q0 = qgm + (size_t)(wid * 32 + s * 16 + g) * DIM;
        const __half* q1 = q0 + (size_t)8 * DIM;
#pragma unroll
        for (int kb = 0; kb < 4; kb++) {
            qf[s][kb][0] = *(const uint32_t*)(q0 + 16 * kb + 2 * t);
            qf[s][kb][1] = *(const uint32_t*)(q1 + 16 * kb + 2 * t);
            qf[s][kb][2] = *(const uint32_t*)(q0 + 16 * kb + 8 + 2 * t);
            qf[s][kb][3] = *(const uint32_t*)(q1 + 16 * kb + 8 + 2 * t);
        }
    }

    #define LOAD_ONE(jt_) do {                                                  \
        const int _buf = (jt_) & 3;                                             \
        const __half* _ks = kgm + (size_t)((jt_) * KT) * DIM;                   \
        const __half* _vs = vgm + (size_t)((jt_) * KT) * DIM;                   \
        uint32_t _kd = sb + (uint32_t)(_buf * K_BUF) * 2u;                      \
        uint32_t _vd = sb + (uint32_t)(VOFF0 + _buf * K_BUF) * 2u;              \
        _Pragma("unroll")                                                       \
        for (int i = 0; i < 4; i++) {                                           \
            int c = tid + i * 128, r = c >> 3, c8 = (c & 7) << 3;               \
            CPA(_kd + (uint32_t)(r * KS + c8) * 2u, _ks + (size_t)r * DIM + c8);\
            CPA(_vd + (uint32_t)(r * KS + c8) * 2u, _vs + (size_t)r * DIM + c8);\
        }                                                                       \
    } while (0)
    #define LOAD2(jt_) do { LOAD_ONE(jt_); LOAD_ONE((jt_) + 1); CPC(); } while (0)

    float O[2][8][4] = {};

    LOAD2(0);

    for (int jt2 = 0; jt2 < NT; jt2 += 2) {
        CPW(0);
        __syncthreads();
        if (jt2 + 2 < NT) LOAD2(jt2 + 2);

#pragma unroll
        for (int j = 0; j < 2; j++) {
            const int jt = jt2 + j;
            const int buf = jt & 3;
            const uint32_t ksb = sb + (uint32_t)(buf * K_BUF) * 2u;
            const uint32_t vsb = sb + (uint32_t)((VOFF0 + buf * K_BUF)) * 2u;

#pragma unroll
            for (int nf2 = 0; nf2 < 4; nf2++) {
                const int n0 = nf2 * 16;

                float Sb[2][2][4] = {};
#pragma unroll
                for (int kb = 0; kb < 4; kb++) {
                    const int k0 = kb * 16;
                    uint32_t r0, r1, r2, r3;
                    LDSM4(r0, r1, r2, r3,
                          ksb + (uint32_t)((n0 + k_row) * KS + k0 + k_col) * 2u);
#pragma unroll
                    for (int s = 0; s < 2; s++) {
                        mma16(Sb[s][0], qf[s][kb], r0, r1);
                        mma16(Sb[s][1], qf[s][kb], r2, r3);
                    }
                }

                uint32_t pb[2][4];
#pragma unroll
                for (int s = 0; s < 2; s++) {
                    pb[s][0] = sig2(Sb[s][0][0], Sb[s][0][1]);
                    pb[s][1] = sig2(Sb[s][0][2], Sb[s][0][3]);
                    pb[s][2] = sig2(Sb[s][1][0], Sb[s][1][1]);
                    pb[s][3] = sig2(Sb[s][1][2], Sb[s][1][3]);
                }

#pragma unroll
                for (int nv = 0; nv < 4; nv++) {
                    const int n0v = nv * 16;
                    uint32_t r0, r1, r2, r3;
                    LDSM4T(r0, r1, r2, r3,
                           vsb + (uint32_t)((n0 + v_row) * KS + n0v + v_col) * 2u);
#pragma unroll
                    for (int s = 0; s < 2; s++) {
                        mma16(O[s][2 * nv],     pb[s], r0, r1);
                        mma16(O[s][2 * nv + 1], pb[s], r2, r3);
                    }
                }
            }
        }
    }

#pragma unroll
    for (int s = 0; s < 2; s++) {
        const int r0 = it * 128 + wid * 32 + s * 16 + g;
        float* og = out + ((size_t)b * N_SEQ + r0) * DIM + h * DK;
#pragma unroll
        for (int nf = 0; nf < 8; nf++) {
            const int d = nf * 8 + 2 * t;
            *(float2*)&og[d] = make_float2(O[s][nf][0], O[s][nf][1]);
            *(float2*)(og + (size_t)8 * DIM + d) = make_float2(O[s][nf][2], O[s][nf][3]);
        }
    }
}

extern "C" void kernel_launch(void* const* d_in, const int* in_sizes, int n_in,
                              void* d_out, int out_size)
{
    const float* x    = (const float*)d_in[0];
    const float* Wq   = (const float*)d_in[1];
    const float* Wk   = (const float*)d_in[2];
    const float* bias = (const float*)d_in[3];
    float* out = (float*)d_out;

    cudaFuncSetAttribute(proj_tc, cudaFuncAttributeMaxDynamicSharedMemorySize, P2_SMEM);
    cudaFuncSetAttribute(attn_tc, cudaFuncAttributeMaxDynamicSharedMemorySize, AT_SMEM);

    prep<<<(NTOT + 1023) / 1024, 256>>>(x, Wq, Wk);
    proj_tc<<<dim3(2 * DIM / 128, M_ROWS / 128), 256, P2_SMEM>>>(bias);
    attn_tc<<<dim3(N_SEQ / 128, NH, B_SZ), 128, AT_SMEM>>>(out);
}

// round 14
// speedup vs baseline: 1.2327x; 1.0129x over previous
#include <cuda_runtime.h>
#include <cuda_fp16.h>
#include <cstdint>

#define B_SZ  4
#define N_SEQ 2048
#define DIM   512
#define NH    8
#define DK    64
#define M_ROWS (B_SZ * N_SEQ)
#define SCALE 0.125f

__device__ __half g_Q[M_ROWS * DIM];
__device__ __half g_K[M_ROWS * DIM];
__device__ __half g_V[M_ROWS * DIM];
__device__ __half g_Wq[DIM * DIM];
__device__ __half g_Wk[DIM * DIM];

// ---------------------------------------------------------------------------
// helpers
// ---------------------------------------------------------------------------
__device__ __forceinline__ uint32_t su32(const void* p) {
    uint32_t a;
    asm("{ .reg .u64 t; cvta.to.shared.u64 t, %1; cvt.u32.u64 %0, t; }" : "=r"(a) : "l"(p));
    return a;
}
#define CPA(sa, gp) asm volatile("cp.async.cg.shared.global [%0], [%1], 16;" :: "r"(sa), "l"(gp))
#define CPC()  asm volatile("cp.async.commit_group;" ::: "memory")
#define CPW(n) asm volatile("cp.async.wait_group %0;" :: "n"(n) : "memory")

__device__ __forceinline__ void mma16(float* d, const uint32_t* a, uint32_t b0, uint32_t b1) {
    asm volatile(
        "mma.sync.aligned.m16n8k16.row.col.f32.f16.f16.f32 "
        "{%0,%1,%2,%3}, {%4,%5,%6,%7}, {%8,%9}, {%0,%1,%2,%3};"
        : "+f"(d[0]), "+f"(d[1]), "+f"(d[2]), "+f"(d[3])
        : "r"(a[0]), "r"(a[1]), "r"(a[2]), "r"(a[3]), "r"(b0), "r"(b1));
}
#define LDSM4(r0, r1, r2, r3, addr)                                            \
    asm volatile("ldmatrix.sync.aligned.m8n8.x4.shared.b16 {%0,%1,%2,%3}, [%4];" \
        : "=r"(r0), "=r"(r1), "=r"(r2), "=r"(r3) : "r"(addr))
#define LDSM4T(r0, r1, r2, r3, addr)                                           \
    asm volatile("ldmatrix.sync.aligned.m8n8.x4.trans.shared.b16 {%0,%1,%2,%3}, [%4];" \
        : "=r"(r0), "=r"(r1), "=r"(r2), "=r"(r3) : "r"(addr))

// Inputs already carry the 0.5 factor (folded into Q projection).
__device__ __forceinline__ uint32_t sig2(float lo, float hi) {
    __half2 v = __floats2half2_rn(lo, hi);
    uint32_t u = *reinterpret_cast<uint32_t*>(&v);
    uint32_t t;
    asm("tanh.approx.f16x2 %0, %1;" : "=r"(t) : "r"(u));
    __half2 th = *reinterpret_cast<__half2*>(&t);
    __half2 hf = __floats2half2_rn(0.5f, 0.5f);
    __half2 r = __hfma2(th, hf, hf);
    return *reinterpret_cast<uint32_t*>(&r);
}

// ---------------------------------------------------------------------------
// prep: x -> g_V, Wq/Wk -> g_Wq/g_Wk (f32->fp16), ILP 4
// ---------------------------------------------------------------------------
#define NX  (M_ROWS * DIM / 4)
#define NW  (DIM * DIM / 4)
#define NTOT (NX + 2 * NW)
__global__ __launch_bounds__(256) void prep(const float* __restrict__ x,
                                            const float* __restrict__ Wq,
                                            const float* __restrict__ Wk) {
    const int base = blockIdx.x * 1024 + threadIdx.x;
#pragma unroll
    for (int j = 0; j < 4; j++) {
        const int i = base + j * 256;
        if (i >= NTOT) break;
        const float* src;
        __half* dst;
        int idx;
        if (i < NX)           { src = x;  dst = g_V;  idx = i; }
        else if (i < NX + NW) { src = Wq; dst = g_Wq; idx = i - NX; }
        else                  { src = Wk; dst = g_Wk; idx = i - NX - NW; }
        float4 v = reinterpret_cast<const float4*>(src)[idx];
        __half2 h0 = __floats2half2_rn(v.x, v.y);
        __half2 h1 = __floats2half2_rn(v.z, v.w);
        uint2 u;
        u.x = *reinterpret_cast<uint32_t*>(&h0);
        u.y = *reinterpret_cast<uint32_t*>(&h1);
        reinterpret_cast<uint2*>(dst)[idx] = u;
    }
}

// ---------------------------------------------------------------------------
// Projection, occ-3 redesign: CTA tile 128(M) x 64(N), warp tile 32x32,
// C = 32 regs/thread, 2-stage cp.async. blockIdx.x = colb*2+which (W L2-resident).
// g_Q = h((x@Wq)*SCALE*0.5 + 0.5*bias), g_K = h(x@Wk)
// smem: 2 x (A[128][72] + B[64][72]) halves = 55,296 B -> 3 CTAs/SM.
// ---------------------------------------------------------------------------
#define P3_AS 72
#define P3_A_SZ (128 * P3_AS)       // 9216 halves
#define P3_B_SZ (64 * P3_AS)        // 4608 halves
#define P3_STG (P3_A_SZ + P3_B_SZ)  // 13824 halves
#define P3_SMEM (2 * P3_STG * 2)    // 55,296 B

__global__ __launch_bounds__(256, 3) void proj_tc(const float* __restrict__ bias)
{
    extern __shared__ __half smh[];
    const uint32_t sb = su32(smh);

    const int which = blockIdx.x & 1;
    const int colb  = blockIdx.x >> 1;          // 0..7 (64-col tiles)
    const __half* W = which ? g_Wk : g_Wq;
    __half* outp = which ? g_K : g_Q;

    const int tid = threadIdx.x;
    const int wid = tid >> 5, lane = tid & 31;
    const int g = lane >> 2, t = lane & 3;
    const int rg = wid >> 1, cg = wid & 1;      // 4 row-groups x 2 col-groups
    const int row0 = blockIdx.y * 128, col0 = colb * 64;

    const int lq = lane >> 3, lr = lane & 7;
    const int a_row = ((lq >> 1) << 3) + lr;    // non-trans (A)
    const int a_col = (lq & 1) << 3;
    const int b_row = ((lq & 1) << 3) + lr;     // trans (B, [k][n] layout)
    const int b_col = (lq >> 1) << 3;

    // per kt: A 128x64 f16 (1024 chunks/256thr = 4 ea), B 64x64 f16 (2 ea)
    #define P3_LOAD(kt, stg) do {                                               \
        const __half* _sa = g_V + (size_t)row0 * DIM + (kt) * 64;               \
        uint32_t _da = sb + (uint32_t)((stg) * P3_STG) * 2u;                    \
        _Pragma("unroll")                                                       \
        for (int i = 0; i < 4; i++) {                                           \
            int c = tid + i * 256, r = c >> 3, c8 = (c & 7) << 3;               \
            CPA(_da + (uint32_t)(r * P3_AS + c8) * 2u, _sa + (size_t)r * DIM + c8); \
        }                                                                       \
        const __half* _sb = W + (size_t)((kt) * 64) * DIM + col0;               \
        uint32_t _db = sb + (uint32_t)((stg) * P3_STG + P3_A_SZ) * 2u;          \
        _Pragma("unroll")                                                       \
        for (int i = 0; i < 2; i++) {                                           \
            int c = tid + i * 256, r = c >> 3, c8 = (c & 7) << 3;               \
            CPA(_db + (uint32_t)(r * P3_AS + c8) * 2u, _sb + (size_t)r * DIM + c8); \
        }                                                                       \
        CPC();                                                                  \
    } while (0)

    float C[2][4][4] = {};   // [strip][colfrag8][4] : 32 rows x 32 cols per warp

    P3_LOAD(0, 0);
    for (int kt = 0; kt < 8; kt++) {
        const int buf = kt & 1;
        if (kt < 7) { P3_LOAD(kt + 1, buf ^ 1); CPW(1); } else { CPW(0); }
        __syncthreads();
        const uint32_t Ab = sb + (uint32_t)(buf * P3_STG) * 2u;
        const uint32_t Bb = sb + (uint32_t)(buf * P3_STG + P3_A_SZ) * 2u;
#pragma unroll
        for (int kb = 0; kb < 4; kb++) {
            const int k0 = kb * 16;
            uint32_t af[2][4];
#pragma unroll
            for (int f = 0; f < 2; f++) {
                uint32_t r0, r1, r2, r3;
                LDSM4(r0, r1, r2, r3,
                      Ab + (uint32_t)((rg * 32 + f * 16 + a_row) * P3_AS + k0 + a_col) * 2u);
                af[f][0] = r0; af[f][1] = r2; af[f][2] = r1; af[f][3] = r3;
            }
#pragma unroll
            for (int nf2 = 0; nf2 < 2; nf2++) {
                uint32_t r0, r1, r2, r3;
                LDSM4T(r0, r1, r2, r3,
                       Bb + (uint32_t)((k0 + b_row) * P3_AS + cg * 32 + nf2 * 16 + b_col) * 2u);
                mma16(C[0][2 * nf2],     af[0], r0, r1);
                mma16(C[0][2 * nf2 + 1], af[0], r2, r3);
                mma16(C[1][2 * nf2],     af[1], r0, r1);
                mma16(C[1][2 * nf2 + 1], af[1], r2, r3);
            }
        }
        __syncthreads();
    }

#pragma unroll
    for (int f = 0; f < 2; f++) {
        const int r = row0 + rg * 32 + f * 16 + g;
#pragma unroll
        for (int cf = 0; cf < 4; cf++) {
            const int cb = col0 + cg * 32 + cf * 8 + 2 * t;
            float v0 = C[f][cf][0], v1 = C[f][cf][1], v2 = C[f][cf][2], v3 = C[f][cf][3];
            if (which == 0) {
                const float hs = 0.5f * SCALE;
                v0 = v0 * hs + 0.5f * bias[cb];     v1 = v1 * hs + 0.5f * bias[cb + 1];
                v2 = v2 * hs + 0.5f * bias[cb];     v3 = v3 * hs + 0.5f * bias[cb + 1];
            }
            *(__half2*)&outp[(size_t)r * DIM + cb]       = __floats2half2_rn(v0, v1);
            *(__half2*)&outp[(size_t)(r + 8) * DIM + cb] = __floats2half2_rn(v2, v3);
        }
    }
}

// ---------------------------------------------------------------------------
// Fused sigmoid attention — EXACT R10 configuration (best measured).
// 4 warps x 32 Q-rows, per-16-key-block pipeline, ring-4 smem, occ 3.
// ---------------------------------------------------------------------------
#define KT  64
#define NT  (N_SEQ / KT)
#define KS  72
#define K_BUF (KT * KS)
#define VOFF0 (4 * K_BUF)
#define AT_SMEM (8 * K_BUF * 2)

__global__ __launch_bounds__(128, 3) void attn_tc(float* __restrict__ out)
{
    extern __shared__ __half smh[];
    const uint32_t sb = su32(smh);
    const int tid = threadIdx.x;
    const int wid = tid >> 5, lane = tid & 31;
    const int g = lane >> 2, t = lane & 3;

    const int it = blockIdx.x, h = blockIdx.y, b = blockIdx.z;
    const size_t base = (size_t)b * N_SEQ * DIM + (size_t)h * DK;
    const __half* qgm = g_Q + base + (size_t)(it * 128) * DIM;
    const __half* kgm = g_K + base;
    const __half* vgm = g_V + base;

    const int lq = lane >> 3, lr = lane & 7;
    const int k_row = ((lq >> 1) << 3) + lr;
    const int k_col = (lq & 1) << 3;
    const int v_row = ((lq & 1) << 3) + lr;
    const int v_col = (lq >> 1) << 3;

    uint32_t qf[2][4][4];
#pragma unroll
    for (int s = 0; s < 2; s++) {
        const __half* q0 = qgm + (size_t)(wid * 32 + s * 16 + g) * DIM;
        const __half* q1 = q0 + (size_t)8 * DIM;
#pragma unroll
        for (int kb = 0; kb < 4; kb++) {
            qf[s][kb][0] = *(const uint32_t*)(q0 + 16 * kb + 2 * t);
            qf[s][kb][1] = *(const uint32_t*)(q1 + 16 * kb + 2 * t);
            qf[s][kb][2] = *(const uint32_t*)(q0 + 16 * kb + 8 + 2 * t);
            qf[s][kb][3] = *(const uint32_t*)(q1 + 16 * kb + 8 + 2 * t);
        }
    }

    #define LOAD_ONE(jt_) do {                                                  \
        const int _buf = (jt_) & 3;                                             \
        const __half* _ks = kgm + (size_t)((jt_) * KT) * DIM;                   \
        const __half* _vs = vgm + (size_t)((jt_) * KT) * DIM;                   \
        uint32_t _kd = sb + (uint32_t)(_buf * K_BUF) * 2u;                      \
        uint32_t _vd = sb + (uint32_t)(VOFF0 + _buf * K_BUF) * 2u;              \
        _Pragma("unroll")                                                       \
        for (int i = 0; i < 4; i++) {                                           \
            int c = tid + i * 128, r = c >> 3, c8 = (c & 7) << 3;               \
            CPA(_kd + (uint32_t)(r * KS + c8) * 2u, _ks + (size_t)r * DIM + c8);\
            CPA(_vd + (uint32_t)(r * KS + c8) * 2u, _vs + (size_t)r * DIM + c8);\
        }                                                                       \
    } while (0)
    #define LOAD2(jt_) do { LOAD_ONE(jt_); LOAD_ONE((jt_) + 1); CPC(); } while (0)

    float O[2][8][4] = {};

    LOAD2(0);

    for (int jt2 = 0; jt2 < NT; jt2 += 2) {
        CPW(0);
        __syncthreads();
        if (jt2 + 2 < NT) LOAD2(jt2 + 2);

#pragma unroll
        for (int j = 0; j < 2; j++) {
            const int jt = jt2 + j;
            const int buf = jt & 3;
            const uint32_t ksb = sb + (uint32_t)(buf * K_BUF) * 2u;
            const uint32_t vsb = sb + (uint32_t)((VOFF0 + buf * K_BUF)) * 2u;

#pragma unroll
            for (int nf2 = 0; nf2 < 4; nf2++) {
                const int n0 = nf2 * 16;

                float Sb[2][2][4] = {};
#pragma unroll
                for (int kb = 0; kb < 4; kb++) {
                    const int k0 = kb * 16;
                    uint32_t r0, r1, r2, r3;
                    LDSM4(r0, r1, r2, r3,
                          ksb + (uint32_t)((n0 + k_row) * KS + k0 + k_col) * 2u);
#pragma unroll
                    for (int s = 0; s < 2; s++) {
                        mma16(Sb[s][0], qf[s][kb], r0, r1);
                        mma16(Sb[s][1], qf[s][kb], r2, r3);
                    }
                }

                uint32_t pb[2][4];
#pragma unroll
                for (int s = 0; s < 2; s++) {
                    pb[s][0] = sig2(Sb[s][0][0], Sb[s][0][1]);
                    pb[s][1] = sig2(Sb[s][0][2], Sb[s][0][3]);
                    pb[s][2] = sig2(Sb[s][1][0], Sb[s][1][1]);
                    pb[s][3] = sig2(Sb[s][1][2], Sb[s][1][3]);
                }

#pragma unroll
                for (int nv = 0; nv < 4; nv++) {
                    const int n0v = nv * 16;
                    uint32_t r0, r1, r2, r3;
                    LDSM4T(r0, r1, r2, r3,
                           vsb + (uint32_t)((n0 + v_row) * KS + n0v + v_col) * 2u);
#pragma unroll
                    for (int s = 0; s < 2; s++) {
                        mma16(O[s][2 * nv],     pb[s], r0, r1);
                        mma16(O[s][2 * nv + 1], pb[s], r2, r3);
                    }
                }
            }
        }
    }

#pragma unroll
    for (int s = 0; s < 2; s++) {
        const int r0 = it * 128 + wid * 32 + s * 16 + g;
        float* og = out + ((size_t)b * N_SEQ + r0) * DIM + h * DK;
#pragma unroll
        for (int nf = 0; nf < 8; nf++) {
            const int d = nf * 8 + 2 * t;
            *(float2*)&og[d] = make_float2(O[s][nf][0], O[s][nf][1]);
            *(float2*)(og + (size_t)8 * DIM + d) = make_float2(O[s][nf][2], O[s][nf][3]);
        }
    }
}

extern "C" void kernel_launch(void* const* d_in, const int* in_sizes, int n_in,
                              void* d_out, int out_size)
{
    const float* x    = (const float*)d_in[0];
    const float* Wq   = (const float*)d_in[1];
    const float* Wk   = (const float*)d_in[2];
    const float* bias = (const float*)d_in[3];
    float* out = (float*)d_out;

    cudaFuncSetAttribute(proj_tc, cudaFuncAttributeMaxDynamicSharedMemorySize, P3_SMEM);
    cudaFuncSetAttribute(attn_tc, cudaFuncAttributeMaxDynamicSharedMemorySize, AT_SMEM);

    prep<<<(NTOT + 1023) / 1024, 256>>>(x, Wq, Wk);
    proj_tc<<<dim3(2 * DIM / 64, M_ROWS / 128), 256, P3_SMEM>>>(bias);
    attn_tc<<<dim3(N_SEQ / 128, NH, B_SZ), 128, AT_SMEM>>>(out);
}